// round 8
// baseline (speedup 1.0000x reference)
#include <cuda_runtime.h>
#include <math.h>

#define NMAT_X 32768
#define C_CLS  128
#define NDIM   64
#define NSQ    4096          // 64*64
#define PITCH  65            // smem pitch (odd -> conflict-free columns)
#define MAXSWEEP 13

// ---- scratch (device globals; no runtime allocation allowed) ----
__device__ float g_logX[134217728];   // 32768 * 4096  (512 MB)
__device__ float g_logP[C_CLS * NSQ];
__device__ float g_Asym[C_CLS * NSQ];
__device__ float g_offs[C_CLS];

// =====================================================================
// A_sym = tril(A,-1) + tril(A,-1)^T + diag(A)
// =====================================================================
__global__ __launch_bounds__(256) void make_asym_k(const float* __restrict__ A,
                                                   float* __restrict__ S) {
    int c = blockIdx.x;
    const float* Ac = A + (size_t)c * NSQ;
    float* Sc = S + (size_t)c * NSQ;
    for (int t = threadIdx.x; t < NSQ; t += 256) {
        int i = t >> 6, j = t & 63;
        float v;
        if (i == j)      v = Ac[t];
        else if (i > j)  v = Ac[i * 64 + j];
        else             v = Ac[j * 64 + i];
        Sc[t] = v;
    }
}

// =====================================================================
// Batched Jacobi eigensolver + logm reconstruction.
// One block (256 threads) per 64x64 SPD matrix.
// EXACT numeric path of the known-passing R1 kernel; only the register
// cap (occupancy) differs.
// =====================================================================
__device__ __forceinline__ void tourney_pair(int r, int i, int* p, int* q) {
    // round-robin tournament over 64 players, player 0 fixed. r in [0,62], i in [0,31]
    if (i == 0) { *p = 0; *q = 1 + r; }
    else {
        *p = 1 + (r + i) % 63;
        *q = 1 + (r - i + 63) % 63;
    }
}

__global__ __launch_bounds__(256, 6) void jacobi_logm_k(const float* __restrict__ in,
                                                        float* __restrict__ out) {
    __shared__ float As[NDIM * PITCH];
    __shared__ float Vs[NDIM * PITCH];
    __shared__ float csA[32], snA[32];
    __shared__ int   ppA[32], qqA[32];
    __shared__ float wsum[8];
    __shared__ float fro2v;
    __shared__ int   convflag;
    __shared__ float ev[64];

    const int tid = threadIdx.x;
    const size_t m = blockIdx.x;
    const float* Xm = in + m * (size_t)NSQ;

    // ---- load A, init V = I, accumulate ||A||_F^2 ----
    float part = 0.f;
    for (int t = tid; t < NSQ; t += 256) {
        int i = t >> 6, j = t & 63;
        float v = Xm[t];
        As[i * PITCH + j] = v;
        Vs[i * PITCH + j] = (i == j) ? 1.f : 0.f;
        part += v * v;
    }
    #pragma unroll
    for (int o = 16; o; o >>= 1) part += __shfl_down_sync(0xffffffffu, part, o);
    if ((tid & 31) == 0) wsum[tid >> 5] = part;
    __syncthreads();
    if (tid == 0) {
        float s = 0.f;
        #pragma unroll
        for (int w = 0; w < 8; ++w) s += wsum[w];
        fro2v = s;
        convflag = 0;
    }
    __syncthreads();

    // ---- Jacobi sweeps ----
    for (int sweep = 0; sweep < MAXSWEEP; ++sweep) {
        if (sweep >= 4) {
            // deterministic off-diagonal norm reduction
            float po = 0.f;
            for (int t = tid; t < NSQ; t += 256) {
                int i = t >> 6, j = t & 63;
                if (i != j) { float v = As[i * PITCH + j]; po += v * v; }
            }
            #pragma unroll
            for (int o = 16; o; o >>= 1) po += __shfl_down_sync(0xffffffffu, po, o);
            if ((tid & 31) == 0) wsum[tid >> 5] = po;
            __syncthreads();
            if (tid == 0) {
                float s = 0.f;
                #pragma unroll
                for (int w = 0; w < 8; ++w) s += wsum[w];
                convflag = (s <= 1e-10f * fro2v) ? 1 : 0;
            }
            __syncthreads();
            if (convflag) break;
        }

        for (int r = 0; r < 63; ++r) {
            // --- phase 1: 32 rotation params (one warp) ---
            if (tid < 32) {
                int p, q;
                tourney_pair(r, tid, &p, &q);
                ppA[tid] = p; qqA[tid] = q;
                float app = As[p * PITCH + p];
                float aqq = As[q * PITCH + q];
                float apq = As[p * PITCH + q];
                float c = 1.f, s = 0.f;
                if (fabsf(apq) > 1e-30f) {
                    float tau = (aqq - app) / (2.0f * apq);
                    float t = 1.0f / (fabsf(tau) + sqrtf(1.0f + tau * tau));
                    if (tau < 0.f) t = -t;
                    c = rsqrtf(1.f + t * t);
                    s = t * c;
                }
                csA[tid] = c; snA[tid] = s;
            }
            __syncthreads();

            // --- phase 2a: A <- J^T A J, 1024 disjoint 2x2 blocks ---
            {
                const int ri = tid >> 3;                 // this thread's row-pair
                const int p1 = ppA[ri], q1 = qqA[ri];
                const float c1 = csA[ri], s1 = snA[ri];
                const int cib = (tid & 7) * 4;
                #pragma unroll
                for (int it = 0; it < 4; ++it) {
                    const int ci = cib + it;
                    const int p2 = ppA[ci], q2 = qqA[ci];
                    const float c2 = csA[ci], s2 = snA[ci];
                    float a00 = As[p1 * PITCH + p2];
                    float a01 = As[p1 * PITCH + q2];
                    float a10 = As[q1 * PITCH + p2];
                    float a11 = As[q1 * PITCH + q2];
                    float t00 = c1 * a00 - s1 * a10;
                    float t01 = c1 * a01 - s1 * a11;
                    float t10 = s1 * a00 + c1 * a10;
                    float t11 = s1 * a01 + c1 * a11;
                    As[p1 * PITCH + p2] = c2 * t00 - s2 * t01;
                    As[p1 * PITCH + q2] = s2 * t00 + c2 * t01;
                    As[q1 * PITCH + p2] = c2 * t10 - s2 * t11;
                    As[q1 * PITCH + q2] = s2 * t10 + c2 * t11;
                }
            }
            // --- phase 2b: V <- V J (columns p,q) ---
            {
                const int pi = tid >> 3;
                const int p = ppA[pi], q = qqA[pi];
                const float c = csA[pi], s = snA[pi];
                const int rb = tid & 7;
                #pragma unroll
                for (int it = 0; it < 8; ++it) {
                    const int row = rb + 8 * it;
                    float vp = Vs[row * PITCH + p];
                    float vq = Vs[row * PITCH + q];
                    Vs[row * PITCH + p] = c * vp - s * vq;
                    Vs[row * PITCH + q] = s * vp + c * vq;
                }
            }
            __syncthreads();
        }
    }

    // ---- eigenvalue logs ----
    if (tid < 64) ev[tid] = logf(fmaxf(As[tid * PITCH + tid], 1e-12f));
    __syncthreads();

    // ---- W = V * diag(log lambda), overwrite As ----
    for (int t = tid; t < NSQ; t += 256) {
        int i = t >> 6, k = t & 63;
        As[i * PITCH + k] = Vs[i * PITCH + k] * ev[k];
    }
    __syncthreads();

    // ---- logX = W V^T, 4x4 register tile per thread, float4 stores ----
    {
        const int bi = tid >> 4;   // 0..15
        const int bj = tid & 15;   // 0..15
        float acc[4][4];
        #pragma unroll
        for (int u = 0; u < 4; ++u)
            #pragma unroll
            for (int v = 0; v < 4; ++v) acc[u][v] = 0.f;
        for (int k = 0; k < 64; ++k) {
            float wv[4], vv[4];
            #pragma unroll
            for (int u = 0; u < 4; ++u) wv[u] = As[(4 * bi + u) * PITCH + k];
            #pragma unroll
            for (int v = 0; v < 4; ++v) vv[v] = Vs[(4 * bj + v) * PITCH + k];
            #pragma unroll
            for (int u = 0; u < 4; ++u)
                #pragma unroll
                for (int v = 0; v < 4; ++v) acc[u][v] += wv[u] * vv[v];
        }
        float* outm = out + m * (size_t)NSQ;
        #pragma unroll
        for (int u = 0; u < 4; ++u) {
            float4 o = make_float4(acc[u][0], acc[u][1], acc[u][2], acc[u][3]);
            *reinterpret_cast<float4*>(&outm[(4 * bi + u) * 64 + 4 * bj]) = o;
        }
    }
}

// =====================================================================
// offs[c] = <logP_c, Asym_c>
// =====================================================================
__global__ __launch_bounds__(256) void make_offs_k(const float* __restrict__ LP,
                                                   const float* __restrict__ S,
                                                   float* __restrict__ offs) {
    __shared__ float ws[8];
    int c = blockIdx.x;
    float part = 0.f;
    for (int t = threadIdx.x; t < NSQ; t += 256)
        part += LP[(size_t)c * NSQ + t] * S[(size_t)c * NSQ + t];
    #pragma unroll
    for (int o = 16; o; o >>= 1) part += __shfl_down_sync(0xffffffffu, part, o);
    if ((threadIdx.x & 31) == 0) ws[threadIdx.x >> 5] = part;
    __syncthreads();
    if (threadIdx.x == 0) {
        float s = 0.f;
        #pragma unroll
        for (int w = 0; w < 8; ++w) s += ws[w];
        offs[c] = s;
    }
}

// =====================================================================
// out[n,c] = sum_k logX[n,k] * Asym[c,k] - offs[c]
// Tile: 128 n-rows x 128 classes per block, 256 threads, 8x8 per thread
// =====================================================================
__global__ __launch_bounds__(256) void logits_gemm_k(const float* __restrict__ LX,
                                                     const float* __restrict__ B,
                                                     const float* __restrict__ offs,
                                                     float* __restrict__ out) {
    __shared__ float Xs[128][33];
    __shared__ float Bs[128][33];
    const int tid = threadIdx.x;
    const int n0 = blockIdx.x * 128;
    const int ti = tid >> 4;   // 0..15
    const int tj = tid & 15;   // 0..15

    float acc[8][8];
    #pragma unroll
    for (int u = 0; u < 8; ++u)
        #pragma unroll
        for (int v = 0; v < 8; ++v) acc[u][v] = 0.f;

    for (int k0 = 0; k0 < NSQ; k0 += 32) {
        #pragma unroll
        for (int it = 0; it < 4; ++it) {
            int f = tid + it * 256;          // 0..1023
            int row = f >> 3;
            int c4 = (f & 7) * 4;
            float4 x = *reinterpret_cast<const float4*>(
                &LX[(size_t)(n0 + row) * NSQ + k0 + c4]);
            Xs[row][c4] = x.x; Xs[row][c4 + 1] = x.y;
            Xs[row][c4 + 2] = x.z; Xs[row][c4 + 3] = x.w;
            float4 b = *reinterpret_cast<const float4*>(
                &B[(size_t)row * NSQ + k0 + c4]);
            Bs[row][c4] = b.x; Bs[row][c4 + 1] = b.y;
            Bs[row][c4 + 2] = b.z; Bs[row][c4 + 3] = b.w;
        }
        __syncthreads();

        #pragma unroll 4
        for (int kk = 0; kk < 32; ++kk) {
            float xr[8], bc[8];
            #pragma unroll
            for (int u = 0; u < 8; ++u) xr[u] = Xs[ti + 16 * u][kk];
            #pragma unroll
            for (int v = 0; v < 8; ++v) bc[v] = Bs[tj + 16 * v][kk];
            #pragma unroll
            for (int u = 0; u < 8; ++u)
                #pragma unroll
                for (int v = 0; v < 8; ++v) acc[u][v] += xr[u] * bc[v];
        }
        __syncthreads();
    }

    float offv[8];
    #pragma unroll
    for (int v = 0; v < 8; ++v) offv[v] = offs[tj + 16 * v];
    #pragma unroll
    for (int u = 0; u < 8; ++u) {
        size_t rowoff = (size_t)(n0 + ti + 16 * u) * C_CLS;
        #pragma unroll
        for (int v = 0; v < 8; ++v)
            out[rowoff + tj + 16 * v] = acc[u][v] - offv[v];
    }
}

// =====================================================================
extern "C" void kernel_launch(void* const* d_in, const int* in_sizes, int n_in,
                              void* d_out, int out_size) {
    // inputs in metadata order: X (32768*4096), P (128*4096), A (128*4096)
    const float* X = (const float*)d_in[0];
    const float* P = (const float*)d_in[1];
    const float* A = (const float*)d_in[2];
    if (n_in == 3) {
        int xi = 0;
        for (int i = 1; i < 3; ++i) if (in_sizes[i] > in_sizes[xi]) xi = i;
        if (xi != 0) {
            const float* ins[3] = {(const float*)d_in[0], (const float*)d_in[1],
                                   (const float*)d_in[2]};
            X = ins[xi];
            int k = 0;
            const float* rest[2];
            for (int i = 0; i < 3; ++i) if (i != xi) rest[k++] = ins[i];
            P = rest[0]; A = rest[1];
        }
    }
    float* out = (float*)d_out;

    float *p_logX = nullptr, *p_logP = nullptr, *p_Asym = nullptr, *p_offs = nullptr;
    cudaGetSymbolAddress((void**)&p_logX, g_logX);
    cudaGetSymbolAddress((void**)&p_logP, g_logP);
    cudaGetSymbolAddress((void**)&p_Asym, g_Asym);
    cudaGetSymbolAddress((void**)&p_offs, g_offs);

    make_asym_k<<<C_CLS, 256>>>(A, p_Asym);
    jacobi_logm_k<<<C_CLS, 256>>>(P, p_logP);
    jacobi_logm_k<<<NMAT_X, 256>>>(X, p_logX);
    make_offs_k<<<C_CLS, 256>>>(p_logP, p_Asym, p_offs);
    logits_gemm_k<<<NMAT_X / 128, 256>>>(p_logX, p_Asym, p_offs, out);
}

// round 9
// speedup vs baseline: 1.4339x; 1.4339x over previous
#include <cuda_runtime.h>
#include <math.h>

#define NMAT_X 32768
#define C_CLS  128
#define NDIM   64
#define NSQ    4096          // 64*64
#define PITCH  65            // smem pitch for A (odd -> conflict-free columns)
#define PITCHV 68            // smem pitch for Vt (16B-aligned float4 rows)
#define MAXSWEEP 13

// ---- scratch (device globals; no runtime allocation allowed) ----
__device__ float g_logX[134217728];   // 32768 * 4096  (512 MB)
__device__ float g_logP[C_CLS * NSQ];
__device__ float g_Asym[C_CLS * NSQ];
__device__ float g_offs[C_CLS];

// =====================================================================
// A_sym = tril(A,-1) + tril(A,-1)^T + diag(A)
// =====================================================================
__global__ __launch_bounds__(256) void make_asym_k(const float* __restrict__ A,
                                                   float* __restrict__ S) {
    int c = blockIdx.x;
    const float* Ac = A + (size_t)c * NSQ;
    float* Sc = S + (size_t)c * NSQ;
    for (int t = threadIdx.x; t < NSQ; t += 256) {
        int i = t >> 6, j = t & 63;
        float v;
        if (i == j)      v = Ac[t];
        else if (i > j)  v = Ac[i * 64 + j];
        else             v = Ac[j * 64 + i];
        Sc[t] = v;
    }
}

// =====================================================================
// Batched Jacobi eigensolver + logm reconstruction.
// One block (256 threads) per 64x64 SPD matrix.
// Numeric path identical to the passing R1/R7 kernel; V is stored
// TRANSPOSED (Vt[col][row]) so phase-2b and reconstruction vectorize,
// and W=V*diag(log l) is fused into the reconstruction (same mul->fma
// rounding sequence). Convergence check is R1-verbatim (reads As only).
// =====================================================================
__device__ __forceinline__ void tourney_pair(int r, int i, int* p, int* q) {
    // round-robin tournament over 64 players, player 0 fixed. r in [0,62], i in [0,31]
    if (i == 0) { *p = 0; *q = 1 + r; }
    else {
        *p = 1 + (r + i) % 63;
        *q = 1 + (r - i + 63) % 63;
    }
}

__global__ __launch_bounds__(256, 6) void jacobi_logm_k(const float* __restrict__ in,
                                                        float* __restrict__ out) {
    __shared__ float As[NDIM * PITCH];
    __shared__ __align__(16) float Vt[NDIM * PITCHV];
    __shared__ float csA[32], snA[32];
    __shared__ int   ppA[32], qqA[32];
    __shared__ float wsum[8];
    __shared__ float fro2v;
    __shared__ int   convflag;
    __shared__ float ev[64];

    const int tid = threadIdx.x;
    const size_t m = blockIdx.x;
    const float* Xm = in + m * (size_t)NSQ;

    // ---- load A, init Vt = I, accumulate ||A||_F^2 ----
    float part = 0.f;
    for (int t = tid; t < NSQ; t += 256) {
        int i = t >> 6, j = t & 63;
        float v = Xm[t];
        As[i * PITCH + j] = v;
        Vt[i * PITCHV + j] = (i == j) ? 1.f : 0.f;   // symmetric identity: Vt=I
        part += v * v;
    }
    #pragma unroll
    for (int o = 16; o; o >>= 1) part += __shfl_down_sync(0xffffffffu, part, o);
    if ((tid & 31) == 0) wsum[tid >> 5] = part;
    __syncthreads();
    if (tid == 0) {
        float s = 0.f;
        #pragma unroll
        for (int w = 0; w < 8; ++w) s += wsum[w];
        fro2v = s;
        convflag = 0;
    }
    __syncthreads();

    // ---- Jacobi sweeps ----
    for (int sweep = 0; sweep < MAXSWEEP; ++sweep) {
        if (sweep >= 4) {
            // deterministic off-diagonal norm reduction (R1-verbatim)
            float po = 0.f;
            for (int t = tid; t < NSQ; t += 256) {
                int i = t >> 6, j = t & 63;
                if (i != j) { float v = As[i * PITCH + j]; po += v * v; }
            }
            #pragma unroll
            for (int o = 16; o; o >>= 1) po += __shfl_down_sync(0xffffffffu, po, o);
            if ((tid & 31) == 0) wsum[tid >> 5] = po;
            __syncthreads();
            if (tid == 0) {
                float s = 0.f;
                #pragma unroll
                for (int w = 0; w < 8; ++w) s += wsum[w];
                convflag = (s <= 1e-10f * fro2v) ? 1 : 0;
            }
            __syncthreads();
            if (convflag) break;
        }

        for (int r = 0; r < 63; ++r) {
            // --- phase 1: 32 rotation params (one warp), IEEE division ---
            if (tid < 32) {
                int p, q;
                tourney_pair(r, tid, &p, &q);
                ppA[tid] = p; qqA[tid] = q;
                float app = As[p * PITCH + p];
                float aqq = As[q * PITCH + q];
                float apq = As[p * PITCH + q];
                float c = 1.f, s = 0.f;
                if (fabsf(apq) > 1e-30f) {
                    float tau = (aqq - app) / (2.0f * apq);
                    float t = 1.0f / (fabsf(tau) + sqrtf(1.0f + tau * tau));
                    if (tau < 0.f) t = -t;
                    c = rsqrtf(1.f + t * t);
                    s = t * c;
                }
                csA[tid] = c; snA[tid] = s;
            }
            __syncthreads();

            // --- phase 2a: A <- J^T A J, 1024 disjoint 2x2 blocks ---
            {
                const int ri = tid >> 3;                 // this thread's row-pair
                const int p1 = ppA[ri], q1 = qqA[ri];
                const float c1 = csA[ri], s1 = snA[ri];
                const int cib = (tid & 7) * 4;
                #pragma unroll
                for (int it = 0; it < 4; ++it) {
                    const int ci = cib + it;
                    const int p2 = ppA[ci], q2 = qqA[ci];
                    const float c2 = csA[ci], s2 = snA[ci];
                    float a00 = As[p1 * PITCH + p2];
                    float a01 = As[p1 * PITCH + q2];
                    float a10 = As[q1 * PITCH + p2];
                    float a11 = As[q1 * PITCH + q2];
                    float t00 = c1 * a00 - s1 * a10;
                    float t01 = c1 * a01 - s1 * a11;
                    float t10 = s1 * a00 + c1 * a10;
                    float t11 = s1 * a01 + c1 * a11;
                    As[p1 * PITCH + p2] = c2 * t00 - s2 * t01;
                    As[p1 * PITCH + q2] = s2 * t00 + c2 * t01;
                    As[q1 * PITCH + p2] = c2 * t10 - s2 * t11;
                    As[q1 * PITCH + q2] = s2 * t10 + c2 * t11;
                }
            }
            // --- phase 2b: Vt rows p,q <- rotation (float4 vectorized) ---
            // Vt[k][i] = V[i][k]; update V[:,p],V[:,q] == Vt rows p,q.
            // Per-element arithmetic identical to scalar version.
            {
                const int pi = tid >> 3;
                const int p = ppA[pi], q = qqA[pi];
                const float c = csA[pi], s = snA[pi];
                const int rb = (tid & 7) * 8;
                float4* vp = reinterpret_cast<float4*>(&Vt[p * PITCHV + rb]);
                float4* vq = reinterpret_cast<float4*>(&Vt[q * PITCHV + rb]);
                #pragma unroll
                for (int h = 0; h < 2; ++h) {
                    float4 a = vp[h], b = vq[h];
                    float4 np, nq;
                    np.x = c * a.x - s * b.x;  nq.x = s * a.x + c * b.x;
                    np.y = c * a.y - s * b.y;  nq.y = s * a.y + c * b.y;
                    np.z = c * a.z - s * b.z;  nq.z = s * a.z + c * b.z;
                    np.w = c * a.w - s * b.w;  nq.w = s * a.w + c * b.w;
                    vp[h] = np; vq[h] = nq;
                }
            }
            __syncthreads();
        }
    }

    // ---- eigenvalue logs ----
    if (tid < 64) ev[tid] = logf(fmaxf(As[tid * PITCH + tid], 1e-12f));
    __syncthreads();

    // ---- logX[i][j] = sum_k (Vt[k][i]*ev[k]) * Vt[k][j]  (fused W) ----
    {
        const int bi = tid >> 4;   // 0..15
        const int bj = tid & 15;   // 0..15
        float acc[4][4];
        #pragma unroll
        for (int u = 0; u < 4; ++u)
            #pragma unroll
            for (int v = 0; v < 4; ++v) acc[u][v] = 0.f;
        for (int k = 0; k < 64; ++k) {
            const float evk = ev[k];
            float4 a = *reinterpret_cast<const float4*>(&Vt[k * PITCHV + 4 * bi]);
            float4 b = *reinterpret_cast<const float4*>(&Vt[k * PITCHV + 4 * bj]);
            float wa[4] = {a.x * evk, a.y * evk, a.z * evk, a.w * evk};
            float vb[4] = {b.x, b.y, b.z, b.w};
            #pragma unroll
            for (int u = 0; u < 4; ++u)
                #pragma unroll
                for (int v = 0; v < 4; ++v) acc[u][v] += wa[u] * vb[v];
        }
        float* outm = out + m * (size_t)NSQ;
        #pragma unroll
        for (int u = 0; u < 4; ++u) {
            float4 o = make_float4(acc[u][0], acc[u][1], acc[u][2], acc[u][3]);
            *reinterpret_cast<float4*>(&outm[(4 * bi + u) * 64 + 4 * bj]) = o;
        }
    }
}

// =====================================================================
// offs[c] = <logP_c, Asym_c>
// =====================================================================
__global__ __launch_bounds__(256) void make_offs_k(const float* __restrict__ LP,
                                                   const float* __restrict__ S,
                                                   float* __restrict__ offs) {
    __shared__ float ws[8];
    int c = blockIdx.x;
    float part = 0.f;
    for (int t = threadIdx.x; t < NSQ; t += 256)
        part += LP[(size_t)c * NSQ + t] * S[(size_t)c * NSQ + t];
    #pragma unroll
    for (int o = 16; o; o >>= 1) part += __shfl_down_sync(0xffffffffu, part, o);
    if ((threadIdx.x & 31) == 0) ws[threadIdx.x >> 5] = part;
    __syncthreads();
    if (threadIdx.x == 0) {
        float s = 0.f;
        #pragma unroll
        for (int w = 0; w < 8; ++w) s += ws[w];
        offs[c] = s;
    }
}

// =====================================================================
// out[n,c] = sum_k logX[n,k] * Asym[c,k] - offs[c]
// Tile: 128 n-rows x 128 classes per block, 256 threads, 8x8 per thread
// =====================================================================
__global__ __launch_bounds__(256) void logits_gemm_k(const float* __restrict__ LX,
                                                     const float* __restrict__ B,
                                                     const float* __restrict__ offs,
                                                     float* __restrict__ out) {
    __shared__ float Xs[128][33];
    __shared__ float Bs[128][33];
    const int tid = threadIdx.x;
    const int n0 = blockIdx.x * 128;
    const int ti = tid >> 4;   // 0..15
    const int tj = tid & 15;   // 0..15

    float acc[8][8];
    #pragma unroll
    for (int u = 0; u < 8; ++u)
        #pragma unroll
        for (int v = 0; v < 8; ++v) acc[u][v] = 0.f;

    for (int k0 = 0; k0 < NSQ; k0 += 32) {
        #pragma unroll
        for (int it = 0; it < 4; ++it) {
            int f = tid + it * 256;          // 0..1023
            int row = f >> 3;
            int c4 = (f & 7) * 4;
            float4 x = *reinterpret_cast<const float4*>(
                &LX[(size_t)(n0 + row) * NSQ + k0 + c4]);
            Xs[row][c4] = x.x; Xs[row][c4 + 1] = x.y;
            Xs[row][c4 + 2] = x.z; Xs[row][c4 + 3] = x.w;
            float4 b = *reinterpret_cast<const float4*>(
                &B[(size_t)row * NSQ + k0 + c4]);
            Bs[row][c4] = b.x; Bs[row][c4 + 1] = b.y;
            Bs[row][c4 + 2] = b.z; Bs[row][c4 + 3] = b.w;
        }
        __syncthreads();

        #pragma unroll 4
        for (int kk = 0; kk < 32; ++kk) {
            float xr[8], bc[8];
            #pragma unroll
            for (int u = 0; u < 8; ++u) xr[u] = Xs[ti + 16 * u][kk];
            #pragma unroll
            for (int v = 0; v < 8; ++v) bc[v] = Bs[tj + 16 * v][kk];
            #pragma unroll
            for (int u = 0; u < 8; ++u)
                #pragma unroll
                for (int v = 0; v < 8; ++v) acc[u][v] += xr[u] * bc[v];
        }
        __syncthreads();
    }

    float offv[8];
    #pragma unroll
    for (int v = 0; v < 8; ++v) offv[v] = offs[tj + 16 * v];
    #pragma unroll
    for (int u = 0; u < 8; ++u) {
        size_t rowoff = (size_t)(n0 + ti + 16 * u) * C_CLS;
        #pragma unroll
        for (int v = 0; v < 8; ++v)
            out[rowoff + tj + 16 * v] = acc[u][v] - offv[v];
    }
}

// =====================================================================
extern "C" void kernel_launch(void* const* d_in, const int* in_sizes, int n_in,
                              void* d_out, int out_size) {
    // inputs in metadata order: X (32768*4096), P (128*4096), A (128*4096)
    const float* X = (const float*)d_in[0];
    const float* P = (const float*)d_in[1];
    const float* A = (const float*)d_in[2];
    if (n_in == 3) {
        int xi = 0;
        for (int i = 1; i < 3; ++i) if (in_sizes[i] > in_sizes[xi]) xi = i;
        if (xi != 0) {
            const float* ins[3] = {(const float*)d_in[0], (const float*)d_in[1],
                                   (const float*)d_in[2]};
            X = ins[xi];
            int k = 0;
            const float* rest[2];
            for (int i = 0; i < 3; ++i) if (i != xi) rest[k++] = ins[i];
            P = rest[0]; A = rest[1];
        }
    }
    float* out = (float*)d_out;

    float *p_logX = nullptr, *p_logP = nullptr, *p_Asym = nullptr, *p_offs = nullptr;
    cudaGetSymbolAddress((void**)&p_logX, g_logX);
    cudaGetSymbolAddress((void**)&p_logP, g_logP);
    cudaGetSymbolAddress((void**)&p_Asym, g_Asym);
    cudaGetSymbolAddress((void**)&p_offs, g_offs);

    make_asym_k<<<C_CLS, 256>>>(A, p_Asym);
    jacobi_logm_k<<<C_CLS, 256>>>(P, p_logP);
    jacobi_logm_k<<<NMAT_X, 256>>>(X, p_logX);
    make_offs_k<<<C_CLS, 256>>>(p_logP, p_Asym, p_offs);
    logits_gemm_k<<<NMAT_X / 128, 256>>>(p_logX, p_Asym, p_offs, out);
}

// round 10
// speedup vs baseline: 1.5557x; 1.0850x over previous
#include <cuda_runtime.h>
#include <math.h>

#define NMAT_X 32768
#define C_CLS  128
#define NDIM   64
#define NSQ    4096          // 64*64
#define PITCH  65            // smem pitch for A (odd -> conflict-free columns)
#define PITCHV 68            // smem pitch for Vt (16B-aligned float4 rows)
#define MAXSWEEP 13

// ---- scratch (device globals; no runtime allocation allowed) ----
__device__ float g_logX[134217728];   // 32768 * 4096  (512 MB)
__device__ float g_logP[C_CLS * NSQ];
__device__ float g_Asym[C_CLS * NSQ];
__device__ float g_offs[C_CLS];

// =====================================================================
// A_sym = tril(A,-1) + tril(A,-1)^T + diag(A)
// =====================================================================
__global__ __launch_bounds__(256) void make_asym_k(const float* __restrict__ A,
                                                   float* __restrict__ S) {
    int c = blockIdx.x;
    const float* Ac = A + (size_t)c * NSQ;
    float* Sc = S + (size_t)c * NSQ;
    for (int t = threadIdx.x; t < NSQ; t += 256) {
        int i = t >> 6, j = t & 63;
        float v;
        if (i == j)      v = Ac[t];
        else if (i > j)  v = Ac[i * 64 + j];
        else             v = Ac[j * 64 + i];
        Sc[t] = v;
    }
}

// =====================================================================
// Batched Jacobi eigensolver + logm reconstruction.
// One block (256 threads) per 64x64 SPD matrix.
// SYMMETRIC storage: only the canonical lower triangle of A is
// maintained. Phase 2a processes the 496 strictly-lower pair-blocks
// (~2 per thread); diagonal 2x2 blocks are updated analytically by the
// rotation warp (app -= t*apq, aqq += t*apq, apq = 0).
// V stored transposed (Vt[col][row]) for float4 updates; W=V*diag(log l)
// fused into reconstruction. Convergence check reads lower triangle x2.
// =====================================================================
__device__ __forceinline__ void tourney_pair(int r, int i, int* p, int* q) {
    // round-robin tournament over 64 players, player 0 fixed. r in [0,62], i in [0,31]
    if (i == 0) { *p = 0; *q = 1 + r; }
    else {
        *p = 1 + (r + i) % 63;
        *q = 1 + (r - i + 63) % 63;
    }
}

__device__ __forceinline__ void decode_tri(int t, int* rp, int* cp) {
    // t in [0,496): rp in [1,31], cp in [0,rp), t = rp*(rp-1)/2 + cp
    int r = (int)((1.f + sqrtf(8.f * (float)t + 1.f)) * 0.5f);
    while (r * (r - 1) / 2 > t) --r;
    while ((r + 1) * r / 2 <= t) ++r;
    *rp = r;
    *cp = t - r * (r - 1) / 2;
}

__global__ __launch_bounds__(256, 6) void jacobi_logm_k(const float* __restrict__ in,
                                                        float* __restrict__ out) {
    __shared__ float As[NDIM * PITCH];
    __shared__ __align__(16) float Vt[NDIM * PITCHV];
    __shared__ float2 cssn[32];
    __shared__ int    pqA[32];
    __shared__ float wsum[8];
    __shared__ float fro2v;
    __shared__ int   convflag;
    __shared__ float ev[64];

    const int tid = threadIdx.x;
    const size_t m = blockIdx.x;
    const float* Xm = in + m * (size_t)NSQ;

    // ---- per-thread canonical block-task assignment (fixed all rounds) ----
    int rp1, cp1, rp2 = -1, cp2 = -1;
    decode_tri(tid, &rp1, &cp1);
    if (tid < 240) decode_tri(tid + 256, &rp2, &cp2);

    // ---- load A, init Vt = I, accumulate ||A||_F^2 ----
    float part = 0.f;
    for (int t = tid; t < NSQ; t += 256) {
        int i = t >> 6, j = t & 63;
        float v = Xm[t];
        As[i * PITCH + j] = v;
        Vt[i * PITCHV + j] = (i == j) ? 1.f : 0.f;
        part += v * v;
    }
    #pragma unroll
    for (int o = 16; o; o >>= 1) part += __shfl_down_sync(0xffffffffu, part, o);
    if ((tid & 31) == 0) wsum[tid >> 5] = part;
    __syncthreads();
    if (tid == 0) {
        float s = 0.f;
        #pragma unroll
        for (int w = 0; w < 8; ++w) s += wsum[w];
        fro2v = s;
        convflag = 0;
    }
    __syncthreads();

    // ---- Jacobi sweeps ----
    for (int sweep = 0; sweep < MAXSWEEP; ++sweep) {
        if (sweep >= 4) {
            // off-diagonal norm: strictly-lower canonical x2
            float po = 0.f;
            for (int t = tid; t < NSQ; t += 256) {
                int i = t >> 6, j = t & 63;
                if (i > j) { float v = As[i * PITCH + j]; po += v * v; }
            }
            #pragma unroll
            for (int o = 16; o; o >>= 1) po += __shfl_down_sync(0xffffffffu, po, o);
            if ((tid & 31) == 0) wsum[tid >> 5] = po;
            __syncthreads();
            if (tid == 0) {
                float s = 0.f;
                #pragma unroll
                for (int w = 0; w < 8; ++w) s += wsum[w];
                convflag = (2.f * s <= 1e-10f * fro2v) ? 1 : 0;
            }
            __syncthreads();
            if (convflag) break;
        }

        for (int r = 0; r < 63; ++r) {
            // --- phase 1: 32 rotation params + analytic diagonal update ---
            if (tid < 32) {
                int p, q;
                tourney_pair(r, tid, &p, &q);
                pqA[tid] = p | (q << 8);
                const int dpa = p * PITCH + p;
                const int dqa = q * PITCH + q;
                const int oqa = (p > q) ? p * PITCH + q : q * PITCH + p;
                float app = As[dpa];
                float aqq = As[dqa];
                float apq = As[oqa];
                float c = 1.f, s = 0.f, tg = 0.f;
                if (fabsf(apq) > 1e-30f) {
                    float tau = (aqq - app) / (2.0f * apq);
                    tg = 1.0f / (fabsf(tau) + sqrtf(1.0f + tau * tau));
                    if (tau < 0.f) tg = -tg;
                    c = rsqrtf(1.f + tg * tg);
                    s = tg * c;
                }
                cssn[tid] = make_float2(c, s);
                float dpq = tg * apq;
                As[dpa] = app - dpq;
                As[dqa] = aqq + dpq;
                As[oqa] = 0.f;
            }
            __syncthreads();

            // --- phase 2a: 496 strictly-lower canonical 2x2 blocks ---
            {
                // task 1
                {
                    const int pq1 = pqA[rp1];
                    const int p1 = pq1 & 255, q1 = pq1 >> 8;
                    const float2 cs1 = cssn[rp1];
                    const int pq2 = pqA[cp1];
                    const int p2 = pq2 & 255, q2 = pq2 >> 8;
                    const float2 cs2 = cssn[cp1];
                    const int a00a = (p1 > p2) ? p1 * PITCH + p2 : p2 * PITCH + p1;
                    const int a01a = (p1 > q2) ? p1 * PITCH + q2 : q2 * PITCH + p1;
                    const int a10a = (q1 > p2) ? q1 * PITCH + p2 : p2 * PITCH + q1;
                    const int a11a = (q1 > q2) ? q1 * PITCH + q2 : q2 * PITCH + q1;
                    float a00 = As[a00a], a01 = As[a01a];
                    float a10 = As[a10a], a11 = As[a11a];
                    float t00 = cs1.x * a00 - cs1.y * a10;
                    float t01 = cs1.x * a01 - cs1.y * a11;
                    float t10 = cs1.y * a00 + cs1.x * a10;
                    float t11 = cs1.y * a01 + cs1.x * a11;
                    As[a00a] = cs2.x * t00 - cs2.y * t01;
                    As[a01a] = cs2.y * t00 + cs2.x * t01;
                    As[a10a] = cs2.x * t10 - cs2.y * t11;
                    As[a11a] = cs2.y * t10 + cs2.x * t11;
                }
                // task 2 (threads 0..239)
                if (rp2 >= 0) {
                    const int pq1 = pqA[rp2];
                    const int p1 = pq1 & 255, q1 = pq1 >> 8;
                    const float2 cs1 = cssn[rp2];
                    const int pq2 = pqA[cp2];
                    const int p2 = pq2 & 255, q2 = pq2 >> 8;
                    const float2 cs2 = cssn[cp2];
                    const int a00a = (p1 > p2) ? p1 * PITCH + p2 : p2 * PITCH + p1;
                    const int a01a = (p1 > q2) ? p1 * PITCH + q2 : q2 * PITCH + p1;
                    const int a10a = (q1 > p2) ? q1 * PITCH + p2 : p2 * PITCH + q1;
                    const int a11a = (q1 > q2) ? q1 * PITCH + q2 : q2 * PITCH + q1;
                    float a00 = As[a00a], a01 = As[a01a];
                    float a10 = As[a10a], a11 = As[a11a];
                    float t00 = cs1.x * a00 - cs1.y * a10;
                    float t01 = cs1.x * a01 - cs1.y * a11;
                    float t10 = cs1.y * a00 + cs1.x * a10;
                    float t11 = cs1.y * a01 + cs1.x * a11;
                    As[a00a] = cs2.x * t00 - cs2.y * t01;
                    As[a01a] = cs2.y * t00 + cs2.x * t01;
                    As[a10a] = cs2.x * t10 - cs2.y * t11;
                    As[a11a] = cs2.y * t10 + cs2.x * t11;
                }
            }
            // --- phase 2b: Vt rows p,q <- rotation (float4 vectorized) ---
            {
                const int pi = tid >> 3;
                const int pqv = pqA[pi];
                const int p = pqv & 255, q = pqv >> 8;
                const float2 cs = cssn[pi];
                const float c = cs.x, s = cs.y;
                const int rb = (tid & 7) * 8;
                float4* vp = reinterpret_cast<float4*>(&Vt[p * PITCHV + rb]);
                float4* vq = reinterpret_cast<float4*>(&Vt[q * PITCHV + rb]);
                #pragma unroll
                for (int h = 0; h < 2; ++h) {
                    float4 a = vp[h], b = vq[h];
                    float4 np, nq;
                    np.x = c * a.x - s * b.x;  nq.x = s * a.x + c * b.x;
                    np.y = c * a.y - s * b.y;  nq.y = s * a.y + c * b.y;
                    np.z = c * a.z - s * b.z;  nq.z = s * a.z + c * b.z;
                    np.w = c * a.w - s * b.w;  nq.w = s * a.w + c * b.w;
                    vp[h] = np; vq[h] = nq;
                }
            }
            __syncthreads();
        }
    }

    // ---- eigenvalue logs ----
    if (tid < 64) ev[tid] = logf(fmaxf(As[tid * PITCH + tid], 1e-12f));
    __syncthreads();

    // ---- logX[i][j] = sum_k (Vt[k][i]*ev[k]) * Vt[k][j]  (fused W) ----
    {
        const int bi = tid >> 4;   // 0..15
        const int bj = tid & 15;   // 0..15
        float acc[4][4];
        #pragma unroll
        for (int u = 0; u < 4; ++u)
            #pragma unroll
            for (int v = 0; v < 4; ++v) acc[u][v] = 0.f;
        for (int k = 0; k < 64; ++k) {
            const float evk = ev[k];
            float4 a = *reinterpret_cast<const float4*>(&Vt[k * PITCHV + 4 * bi]);
            float4 b = *reinterpret_cast<const float4*>(&Vt[k * PITCHV + 4 * bj]);
            float wa[4] = {a.x * evk, a.y * evk, a.z * evk, a.w * evk};
            float vb[4] = {b.x, b.y, b.z, b.w};
            #pragma unroll
            for (int u = 0; u < 4; ++u)
                #pragma unroll
                for (int v = 0; v < 4; ++v) acc[u][v] += wa[u] * vb[v];
        }
        float* outm = out + m * (size_t)NSQ;
        #pragma unroll
        for (int u = 0; u < 4; ++u) {
            float4 o = make_float4(acc[u][0], acc[u][1], acc[u][2], acc[u][3]);
            *reinterpret_cast<float4*>(&outm[(4 * bi + u) * 64 + 4 * bj]) = o;
        }
    }
}

// =====================================================================
// offs[c] = <logP_c, Asym_c>
// =====================================================================
__global__ __launch_bounds__(256) void make_offs_k(const float* __restrict__ LP,
                                                   const float* __restrict__ S,
                                                   float* __restrict__ offs) {
    __shared__ float ws[8];
    int c = blockIdx.x;
    float part = 0.f;
    for (int t = threadIdx.x; t < NSQ; t += 256)
        part += LP[(size_t)c * NSQ + t] * S[(size_t)c * NSQ + t];
    #pragma unroll
    for (int o = 16; o; o >>= 1) part += __shfl_down_sync(0xffffffffu, part, o);
    if ((threadIdx.x & 31) == 0) ws[threadIdx.x >> 5] = part;
    __syncthreads();
    if (threadIdx.x == 0) {
        float s = 0.f;
        #pragma unroll
        for (int w = 0; w < 8; ++w) s += ws[w];
        offs[c] = s;
    }
}

// =====================================================================
// out[n,c] = sum_k logX[n,k] * Asym[c,k] - offs[c]
// Tile: 128 n-rows x 128 classes per block, 256 threads, 8x8 per thread
// =====================================================================
__global__ __launch_bounds__(256) void logits_gemm_k(const float* __restrict__ LX,
                                                     const float* __restrict__ B,
                                                     const float* __restrict__ offs,
                                                     float* __restrict__ out) {
    __shared__ float Xs[128][33];
    __shared__ float Bs[128][33];
    const int tid = threadIdx.x;
    const int n0 = blockIdx.x * 128;
    const int ti = tid >> 4;   // 0..15
    const int tj = tid & 15;   // 0..15

    float acc[8][8];
    #pragma unroll
    for (int u = 0; u < 8; ++u)
        #pragma unroll
        for (int v = 0; v < 8; ++v) acc[u][v] = 0.f;

    for (int k0 = 0; k0 < NSQ; k0 += 32) {
        #pragma unroll
        for (int it = 0; it < 4; ++it) {
            int f = tid + it * 256;          // 0..1023
            int row = f >> 3;
            int c4 = (f & 7) * 4;
            float4 x = *reinterpret_cast<const float4*>(
                &LX[(size_t)(n0 + row) * NSQ + k0 + c4]);
            Xs[row][c4] = x.x; Xs[row][c4 + 1] = x.y;
            Xs[row][c4 + 2] = x.z; Xs[row][c4 + 3] = x.w;
            float4 b = *reinterpret_cast<const float4*>(
                &B[(size_t)row * NSQ + k0 + c4]);
            Bs[row][c4] = b.x; Bs[row][c4 + 1] = b.y;
            Bs[row][c4 + 2] = b.z; Bs[row][c4 + 3] = b.w;
        }
        __syncthreads();

        #pragma unroll 4
        for (int kk = 0; kk < 32; ++kk) {
            float xr[8], bc[8];
            #pragma unroll
            for (int u = 0; u < 8; ++u) xr[u] = Xs[ti + 16 * u][kk];
            #pragma unroll
            for (int v = 0; v < 8; ++v) bc[v] = Bs[tj + 16 * v][kk];
            #pragma unroll
            for (int u = 0; u < 8; ++u)
                #pragma unroll
                for (int v = 0; v < 8; ++v) acc[u][v] += xr[u] * bc[v];
        }
        __syncthreads();
    }

    float offv[8];
    #pragma unroll
    for (int v = 0; v < 8; ++v) offv[v] = offs[tj + 16 * v];
    #pragma unroll
    for (int u = 0; u < 8; ++u) {
        size_t rowoff = (size_t)(n0 + ti + 16 * u) * C_CLS;
        #pragma unroll
        for (int v = 0; v < 8; ++v)
            out[rowoff + tj + 16 * v] = acc[u][v] - offv[v];
    }
}

// =====================================================================
extern "C" void kernel_launch(void* const* d_in, const int* in_sizes, int n_in,
                              void* d_out, int out_size) {
    // inputs in metadata order: X (32768*4096), P (128*4096), A (128*4096)
    const float* X = (const float*)d_in[0];
    const float* P = (const float*)d_in[1];
    const float* A = (const float*)d_in[2];
    if (n_in == 3) {
        int xi = 0;
        for (int i = 1; i < 3; ++i) if (in_sizes[i] > in_sizes[xi]) xi = i;
        if (xi != 0) {
            const float* ins[3] = {(const float*)d_in[0], (const float*)d_in[1],
                                   (const float*)d_in[2]};
            X = ins[xi];
            int k = 0;
            const float* rest[2];
            for (int i = 0; i < 3; ++i) if (i != xi) rest[k++] = ins[i];
            P = rest[0]; A = rest[1];
        }
    }
    float* out = (float*)d_out;

    float *p_logX = nullptr, *p_logP = nullptr, *p_Asym = nullptr, *p_offs = nullptr;
    cudaGetSymbolAddress((void**)&p_logX, g_logX);
    cudaGetSymbolAddress((void**)&p_logP, g_logP);
    cudaGetSymbolAddress((void**)&p_Asym, g_Asym);
    cudaGetSymbolAddress((void**)&p_offs, g_offs);

    make_asym_k<<<C_CLS, 256>>>(A, p_Asym);
    jacobi_logm_k<<<C_CLS, 256>>>(P, p_logP);
    jacobi_logm_k<<<NMAT_X, 256>>>(X, p_logX);
    make_offs_k<<<C_CLS, 256>>>(p_logP, p_Asym, p_offs);
    logits_gemm_k<<<NMAT_X / 128, 256>>>(p_logX, p_Asym, p_offs, out);
}